// round 5
// baseline (speedup 1.0000x reference)
#include <cuda_runtime.h>
#include <cuda_bf16.h>
#include <cstdint>
#include <math.h>

// ---------------------------------------------------------------------------
// Round 5: HMMA bf16 hi/lo GEMM, 4 warps/CTA, warp tile 64x32 (fewer bigger
// warps -> 25% less ldsm traffic), 2-stage cp.async, 4 CTAs/SM.
// ---------------------------------------------------------------------------

#define M_TOT   6272
#define CDIM    512
#define HW      196
#define BATCH   32
#define HIDN    128
#define AANCH   3
#define NELEM   (M_TOT * CDIM)
#define NLAYER  18

#define BM 128
#define BN 64
#define BK 32
#define KSTAGES 16
// stage layout: 64B rows, SW64 swizzle
#define SA_HI 0
#define SA_LO 8192
#define SB_HI 16384
#define SB_LO 20480
#define STAGE_BYTES 24576
#define NPIPE 2
#define SMEM_DYN (NPIPE * STAGE_BYTES + 128)

__device__ float g_bufA[NELEM];
__device__ float g_anc0[NELEM];
__device__ float g_anc1[NELEM];
__device__ float g_anc2[NELEM];
__device__ float g_gates[BATCH * AANCH * CDIM];
__device__ __nv_bfloat16 g_Ahi[2 * NELEM];
__device__ __nv_bfloat16 g_Alo[2 * NELEM];
__device__ __nv_bfloat16 g_Whi[NLAYER * CDIM * CDIM];  // [l][n][k]
__device__ __nv_bfloat16 g_Wlo[NLAYER * CDIM * CDIM];

// ---------------------------------------------------------------------------
__device__ __forceinline__ uint32_t sw64(uint32_t off) {
    return off ^ ((off >> 3) & 0x30);
}
__device__ __forceinline__ void cpa16(uint32_t s, const void* g) {
    asm volatile("cp.async.cg.shared.global [%0], [%1], 16;" :: "r"(s), "l"(g));
}
__device__ __forceinline__ void cpa_commit() {
    asm volatile("cp.async.commit_group;" ::: "memory");
}
__device__ __forceinline__ void cpa_wait1() {
    asm volatile("cp.async.wait_group 1;" ::: "memory");
}
__device__ __forceinline__ void ldsm_x4(uint32_t& r0, uint32_t& r1, uint32_t& r2,
                                        uint32_t& r3, uint32_t a) {
    asm volatile("ldmatrix.sync.aligned.m8n8.x4.shared.b16 {%0,%1,%2,%3}, [%4];"
                 : "=r"(r0), "=r"(r1), "=r"(r2), "=r"(r3) : "r"(a));
}
__device__ __forceinline__ void mma_bf16(float* c, const uint32_t* a, const uint32_t* b) {
    asm volatile(
        "mma.sync.aligned.m16n8k16.row.col.f32.bf16.bf16.f32 "
        "{%0,%1,%2,%3},{%4,%5,%6,%7},{%8,%9},{%0,%1,%2,%3};"
        : "+f"(c[0]), "+f"(c[1]), "+f"(c[2]), "+f"(c[3])
        : "r"(a[0]), "r"(a[1]), "r"(a[2]), "r"(a[3]), "r"(b[0]), "r"(b[1]));
}
__device__ __forceinline__ float gelu_fast(float x) {
    float u = 0.7978845608028654f * fmaf(0.044715f * x, x * x, x);
    float e = __expf(2.0f * u);
    return 0.5f * x * (1.0f + (1.0f - 2.0f / (e + 1.0f)));
}
__device__ __forceinline__ float gelu_tanh(float x) {
    float x3 = x * x * x;
    return 0.5f * x * (1.0f + tanhf(0.7978845608028654f * (x + 0.044715f * x3)));
}
__device__ __forceinline__ uint32_t pack_bf2(float a, float b) {
    __nv_bfloat162 t = __floats2bfloat162_rn(a, b);
    return *reinterpret_cast<uint32_t*>(&t);
}
__device__ __forceinline__ __nv_bfloat162 split_hi2(float a, float b, float& la, float& lb) {
    __nv_bfloat16 ha = __float2bfloat16(a);
    __nv_bfloat16 hb = __float2bfloat16(b);
    la = a - __bfloat162float(ha);
    lb = b - __bfloat162float(hb);
    __nv_bfloat162 h; h.x = ha; h.y = hb;
    return h;
}

// ---------------------------------------------------------------------------
// GEMM: 128 thr, 4 warps (2m x 2n), warp tile 64x32, 2-stage pipeline.
// ---------------------------------------------------------------------------
__global__ __launch_bounds__(128, 4)
void gemm_hmma(const __nv_bfloat16* __restrict__ aHi, const __nv_bfloat16* __restrict__ aLo,
               const __nv_bfloat16* __restrict__ bHi, const __nv_bfloat16* __restrict__ bLo,
               const float* __restrict__ bias,
               float* __restrict__ out,
               __nv_bfloat16* __restrict__ nHi, __nv_bfloat16* __restrict__ nLo) {
    extern __shared__ char smraw[];
    const uint32_t sb = (uint32_t)__cvta_generic_to_shared(smraw);

    const int t = threadIdx.x;
    const int lane = t & 31;
    const int w = t >> 5;
    const int wm = (w >> 1) * 64;       // 2 warps in m
    const int wn = (w & 1) * 32;        // 2 warps in n
    const int bm = blockIdx.x * BM;
    const int bn = blockIdx.y * BN;

    const int lrow = t >> 2;            // 0..31
    const int lchk = t & 3;             // 16B chunk in 64B row

    auto load_stage = [&](int s, int buf) {
        const int k0 = s * BK;
        const uint32_t stg = sb + (uint32_t)buf * STAGE_BYTES;
#pragma unroll
        for (int p = 0; p < 4; ++p) {
            const int row = p * 32 + lrow;                      // 0..127
            const uint32_t so = sw64((uint32_t)row * 64 + lchk * 16);
            const size_t ga = (size_t)(bm + row) * CDIM + k0 + lchk * 8;
            cpa16(stg + SA_HI + so, aHi + ga);
            cpa16(stg + SA_LO + so, aLo + ga);
        }
#pragma unroll
        for (int p = 0; p < 2; ++p) {
            const int row = p * 32 + lrow;                      // 0..63
            const uint32_t so = sw64((uint32_t)row * 64 + lchk * 16);
            const size_t gb = (size_t)(bn + row) * CDIM + k0 + lchk * 8;
            cpa16(stg + SB_HI + so, bHi + gb);
            cpa16(stg + SB_LO + so, bLo + gb);
        }
    };

    // ldmatrix base offsets (unswizzled)
    uint32_t a_off[4];
#pragma unroll
    for (int mi = 0; mi < 4; ++mi)
        a_off[mi] = (uint32_t)(wm + mi * 16 + (lane & 15)) * 64 + ((lane >> 4) & 1) * 16;
    uint32_t b_off[2];
#pragma unroll
    for (int g = 0; g < 2; ++g)
        b_off[g] = (uint32_t)(wn + g * 16 + ((lane >> 4) & 1) * 8 + (lane & 7)) * 64 +
                   ((lane >> 3) & 1) * 16;

    float acc[4][4][4];
#pragma unroll
    for (int mi = 0; mi < 4; ++mi)
#pragma unroll
        for (int nf = 0; nf < 4; ++nf)
#pragma unroll
            for (int r = 0; r < 4; ++r) acc[mi][nf][r] = 0.0f;

    load_stage(0, 0); cpa_commit();
    load_stage(1, 1); cpa_commit();

#pragma unroll 1
    for (int s = 0; s < KSTAGES; ++s) {
        cpa_wait1();
        __syncthreads();
        const int buf = s & 1;
        const uint32_t stg = sb + (uint32_t)buf * STAGE_BYTES;

#pragma unroll
        for (int kk = 0; kk < 2; ++kk) {
            const uint32_t kb = kk * 32;
            uint32_t ah[4][4], al[4][4], bb[2][4];
            // load ah + bh, do hi*hi
#pragma unroll
            for (int mi = 0; mi < 4; ++mi)
                ldsm_x4(ah[mi][0], ah[mi][1], ah[mi][2], ah[mi][3],
                        stg + SA_HI + sw64(a_off[mi] + kb));
#pragma unroll
            for (int g = 0; g < 2; ++g)
                ldsm_x4(bb[g][0], bb[g][1], bb[g][2], bb[g][3],
                        stg + SB_HI + sw64(b_off[g] + kb));
#pragma unroll
            for (int mi = 0; mi < 4; ++mi)
#pragma unroll
                for (int nf = 0; nf < 4; ++nf)
                    mma_bf16(acc[mi][nf], ah[mi], &bb[nf >> 1][(nf & 1) * 2]);
            // load al, do lo*hi (bb still = bh)
#pragma unroll
            for (int mi = 0; mi < 4; ++mi)
                ldsm_x4(al[mi][0], al[mi][1], al[mi][2], al[mi][3],
                        stg + SA_LO + sw64(a_off[mi] + kb));
#pragma unroll
            for (int mi = 0; mi < 4; ++mi)
#pragma unroll
                for (int nf = 0; nf < 4; ++nf)
                    mma_bf16(acc[mi][nf], al[mi], &bb[nf >> 1][(nf & 1) * 2]);
            // reload bb = bl, do hi*lo
#pragma unroll
            for (int g = 0; g < 2; ++g)
                ldsm_x4(bb[g][0], bb[g][1], bb[g][2], bb[g][3],
                        stg + SB_LO + sw64(b_off[g] + kb));
#pragma unroll
            for (int mi = 0; mi < 4; ++mi)
#pragma unroll
                for (int nf = 0; nf < 4; ++nf)
                    mma_bf16(acc[mi][nf], ah[mi], &bb[nf >> 1][(nf & 1) * 2]);
        }
        __syncthreads();
        if (s + 2 < KSTAGES) load_stage(s + 2, buf);
        cpa_commit();
    }

    // epilogue
    const int r0 = bm + wm + (lane >> 2);
    const int cbase = bn + wn + (lane & 3) * 2;
#pragma unroll
    for (int mi = 0; mi < 4; ++mi) {
#pragma unroll
        for (int nf = 0; nf < 4; ++nf) {
            const int c = cbase + nf * 8;
            const float2 bv = *reinterpret_cast<const float2*>(&bias[c]);
            const int ra = r0 + mi * 16;
            const int rb = ra + 8;
            float v0 = gelu_fast(acc[mi][nf][0] + bv.x);
            float v1 = gelu_fast(acc[mi][nf][1] + bv.y);
            float v2 = gelu_fast(acc[mi][nf][2] + bv.x);
            float v3 = gelu_fast(acc[mi][nf][3] + bv.y);
            if (out) {
                *reinterpret_cast<float2*>(&out[(size_t)ra * CDIM + c]) = make_float2(v0, v1);
                *reinterpret_cast<float2*>(&out[(size_t)rb * CDIM + c]) = make_float2(v2, v3);
            }
            if (nHi) {
                float l0, l1, l2, l3;
                __nv_bfloat162 h01 = split_hi2(v0, v1, l0, l1);
                __nv_bfloat162 h23 = split_hi2(v2, v3, l2, l3);
                *reinterpret_cast<__nv_bfloat162*>(&nHi[(size_t)ra * CDIM + c]) = h01;
                *reinterpret_cast<__nv_bfloat162*>(&nHi[(size_t)rb * CDIM + c]) = h23;
                *reinterpret_cast<uint32_t*>(&nLo[(size_t)ra * CDIM + c]) = pack_bf2(l0, l1);
                *reinterpret_cast<uint32_t*>(&nLo[(size_t)rb * CDIM + c]) = pack_bf2(l2, l3);
            }
        }
    }
}

// ---------------------------------------------------------------------------
__global__ void convert_x(const float* __restrict__ x,
                          __nv_bfloat16* __restrict__ hi, __nv_bfloat16* __restrict__ lo) {
    int i = blockIdx.x * blockDim.x + threadIdx.x;
    if (i >= NELEM / 4) return;
    float4 v = reinterpret_cast<const float4*>(x)[i];
    float l0, l1, l2, l3;
    __nv_bfloat162 h01 = split_hi2(v.x, v.y, l0, l1);
    __nv_bfloat162 h23 = split_hi2(v.z, v.w, l2, l3);
    reinterpret_cast<uint2*>(hi)[i] = make_uint2(*reinterpret_cast<uint32_t*>(&h01),
                                                 *reinterpret_cast<uint32_t*>(&h23));
    reinterpret_cast<uint2*>(lo)[i] = make_uint2(pack_bf2(l0, l1), pack_bf2(l2, l3));
}

__global__ void convert_w(const float* __restrict__ W,
                          __nv_bfloat16* __restrict__ whi, __nv_bfloat16* __restrict__ wlo) {
    __shared__ float tile[32][33];
    const int l = blockIdx.z;
    const int kt = blockIdx.y * 32;
    const int nt = blockIdx.x * 32;
    const int tx = threadIdx.x, ty = threadIdx.y;
    const size_t lb = (size_t)l * CDIM * CDIM;
#pragma unroll
    for (int q = 0; q < 4; ++q)
        tile[ty + 8 * q][tx] = W[lb + (size_t)(kt + ty + 8 * q) * CDIM + nt + tx];
    __syncthreads();
#pragma unroll
    for (int q = 0; q < 4; ++q) {
        float v = tile[tx][ty + 8 * q];
        __nv_bfloat16 h = __float2bfloat16(v);
        size_t idx = lb + (size_t)(nt + ty + 8 * q) * CDIM + kt + tx;
        whi[idx] = h;
        wlo[idx] = __float2bfloat16(v - __bfloat162float(h));
    }
}

// ---------------------------------------------------------------------------
__global__ __launch_bounds__(128)
void gate_kernel(const float* __restrict__ act,
                 const float* __restrict__ fc1w, const float* __restrict__ fc1b,
                 const float* __restrict__ fc2w, const float* __restrict__ fc2b,
                 float* __restrict__ gates) {
    __shared__ float ps[CDIM];
    __shared__ float hs[HIDN];
    __shared__ float lg[AANCH * CDIM];
    const int b = blockIdx.x;
    const int t = threadIdx.x;

    {
        const float* p = act + (size_t)b * HW * CDIM + t * 4;
        float4 s = make_float4(0.f, 0.f, 0.f, 0.f);
#pragma unroll 4
        for (int r = 0; r < HW; ++r) {
            float4 v = *reinterpret_cast<const float4*>(p + (size_t)r * CDIM);
            s.x += v.x; s.y += v.y; s.z += v.z; s.w += v.w;
        }
        const float inv = 1.0f / (float)HW;
        *reinterpret_cast<float4*>(&ps[t * 4]) =
            make_float4(s.x * inv, s.y * inv, s.z * inv, s.w * inv);
    }
    __syncthreads();

    float acc = fc1b[t];
#pragma unroll 8
    for (int k = 0; k < CDIM; ++k)
        acc = fmaf(ps[k], fc1w[k * HIDN + t], acc);
    hs[t] = gelu_tanh(acc);
    __syncthreads();

    for (int j = t; j < AANCH * CDIM; j += 128) {
        float a2 = fc2b[j];
#pragma unroll 8
        for (int k = 0; k < HIDN; ++k)
            a2 = fmaf(hs[k], fc2w[k * (AANCH * CDIM) + j], a2);
        lg[j] = a2;
    }
    __syncthreads();

    for (int c = t; c < CDIM; c += 128) {
        float l0 = lg[c], l1 = lg[CDIM + c], l2 = lg[2 * CDIM + c];
        float m = fmaxf(l0, fmaxf(l1, l2));
        float e0 = expf(l0 - m), e1 = expf(l1 - m), e2 = expf(l2 - m);
        float inv = 1.0f / (e0 + e1 + e2);
        gates[b * AANCH * CDIM + c]            = e0 * inv;
        gates[b * AANCH * CDIM + CDIM + c]     = e1 * inv;
        gates[b * AANCH * CDIM + 2 * CDIM + c] = e2 * inv;
    }
}

__global__ void route_kernel(float* __restrict__ nx,
                             const float* __restrict__ a0,
                             const float* __restrict__ a1,
                             const float* __restrict__ a2,
                             const float* __restrict__ gates,
                             const float* __restrict__ gammas, int tgt,
                             __nv_bfloat16* __restrict__ nhi,
                             __nv_bfloat16* __restrict__ nlo) {
    const int i = blockIdx.x * blockDim.x + threadIdx.x;
    if (i >= NELEM / 4) return;
    const float gamma = gammas[tgt];
    const int per_b = HW * CDIM / 4;
    const int b = i / per_b;
    const int c4 = i & (CDIM / 4 - 1);

    const float4 g0 = *reinterpret_cast<const float4*>(&gates[b * AANCH * CDIM + c4 * 4]);
    const float4 g1 = *reinterpret_cast<const float4*>(&gates[b * AANCH * CDIM + CDIM + c4 * 4]);
    const float4 g2 = *reinterpret_cast<const float4*>(&gates[b * AANCH * CDIM + 2 * CDIM + c4 * 4]);

    float4 v  = reinterpret_cast<float4*>(nx)[i];
    float4 x0 = reinterpret_cast<const float4*>(a0)[i];
    float4 x1 = reinterpret_cast<const float4*>(a1)[i];
    float4 x2 = reinterpret_cast<const float4*>(a2)[i];

    v.x += gamma * (g0.x * x0.x + g1.x * x1.x + g2.x * x2.x);
    v.y += gamma * (g0.y * x0.y + g1.y * x1.y + g2.y * x2.y);
    v.z += gamma * (g0.z * x0.z + g1.z * x1.z + g2.z * x2.z);
    v.w += gamma * (g0.w * x0.w + g1.w * x1.w + g2.w * x2.w);

    reinterpret_cast<float4*>(nx)[i] = v;

    if (nhi) {
        float l0, l1, l2, l3;
        __nv_bfloat162 h01 = split_hi2(v.x, v.y, l0, l1);
        __nv_bfloat162 h23 = split_hi2(v.z, v.w, l2, l3);
        reinterpret_cast<uint2*>(nhi)[i] = make_uint2(*reinterpret_cast<uint32_t*>(&h01),
                                                      *reinterpret_cast<uint32_t*>(&h23));
        reinterpret_cast<uint2*>(nlo)[i] = make_uint2(pack_bf2(l0, l1), pack_bf2(l2, l3));
    }
}

// ---------------------------------------------------------------------------
extern "C" void kernel_launch(void* const* d_in, const int* in_sizes, int n_in,
                              void* d_out, int out_size) {
    const float* x   = (const float*)d_in[0];
    const float* bw  = (const float*)d_in[1];
    const float* bb  = (const float*)d_in[2];
    const float* f1w = (const float*)d_in[3];
    const float* f1b = (const float*)d_in[4];
    const float* f2w = (const float*)d_in[5];
    const float* f2b = (const float*)d_in[6];
    const float* gam = (const float*)d_in[7];

    float *bufA, *anc0, *anc1, *anc2, *gates;
    __nv_bfloat16 *ahi, *alo, *whi, *wlo;
    cudaGetSymbolAddress((void**)&bufA,  g_bufA);
    cudaGetSymbolAddress((void**)&anc0,  g_anc0);
    cudaGetSymbolAddress((void**)&anc1,  g_anc1);
    cudaGetSymbolAddress((void**)&anc2,  g_anc2);
    cudaGetSymbolAddress((void**)&gates, g_gates);
    cudaGetSymbolAddress((void**)&ahi,   g_Ahi);
    cudaGetSymbolAddress((void**)&alo,   g_Alo);
    cudaGetSymbolAddress((void**)&whi,   g_Whi);
    cudaGetSymbolAddress((void**)&wlo,   g_Wlo);

    cudaFuncSetAttribute(gemm_hmma, cudaFuncAttributeMaxDynamicSharedMemorySize, SMEM_DYN);

    convert_w<<<dim3(CDIM / 32, CDIM / 32, NLAYER), dim3(32, 8)>>>(bw, whi, wlo);
    convert_x<<<(NELEM / 4 + 255) / 256, 256>>>(x, ahi, alo);

    const dim3 gemm_grid(M_TOT / BM, CDIM / BN);   // 49 x 8
    int tcount = 0;
    for (int i = 0; i < NLAYER; ++i) {
        float* dst;
        if      (i == 1)  dst = anc0;
        else if (i == 4)  dst = anc1;
        else if (i == 9)  dst = anc2;
        else if (i == 17) dst = (float*)d_out;
        else if (i == 11 || i == 14) dst = bufA;
        else              dst = nullptr;

        const int inS  = i & 1;
        const int outS = (i + 1) & 1;
        const bool last = (i == 17);
        __nv_bfloat16* nhi = last ? nullptr : ahi + (size_t)outS * NELEM;
        __nv_bfloat16* nlo = last ? nullptr : alo + (size_t)outS * NELEM;

        gemm_hmma<<<gemm_grid, 128, SMEM_DYN>>>(
            ahi + (size_t)inS * NELEM, alo + (size_t)inS * NELEM,
            whi + (size_t)i * CDIM * CDIM, wlo + (size_t)i * CDIM * CDIM,
            bb + (size_t)i * CDIM, dst, nhi, nlo);

        if (i == 11 || i == 14 || i == 17) {
            const int tt = tcount++;
            gate_kernel<<<BATCH, 128>>>(dst,
                                        f1w + (size_t)tt * CDIM * HIDN,
                                        f1b + (size_t)tt * HIDN,
                                        f2w + (size_t)tt * HIDN * AANCH * CDIM,
                                        f2b + (size_t)tt * AANCH * CDIM,
                                        gates);
            route_kernel<<<(NELEM / 4 + 255) / 256, 256>>>(dst, anc0, anc1, anc2,
                                                           gates, gam, tt, nhi, nlo);
        }
    }
}

// round 6
// speedup vs baseline: 1.0649x; 1.0649x over previous
#include <cuda_runtime.h>
#include <cuda_fp16.h>
#include <cstdint>
#include <math.h>

// ---------------------------------------------------------------------------
// Round 6: R3 config (proven best) + fp16 hi/lo split (vs bf16) + software-
// pipelined fragment loads (ldsm issued ahead of MMA bursts).
// ---------------------------------------------------------------------------

#define M_TOT   6272
#define CDIM    512
#define HW      196
#define BATCH   32
#define HIDN    128
#define AANCH   3
#define NELEM   (M_TOT * CDIM)
#define NLAYER  18

#define BM 128
#define BN 64
#define BK 64
#define KSTAGES 8
// smem stage layout (128B rows, SW128 swizzle)
#define SA_HI 0
#define SA_LO 16384
#define SB_HI 32768
#define SB_LO 40960
#define STAGE_BYTES 49152
#define SMEM_DYN (1024 + 2 * STAGE_BYTES)

__device__ float g_bufA[NELEM];
__device__ float g_anc0[NELEM];
__device__ float g_anc1[NELEM];
__device__ float g_anc2[NELEM];
__device__ float g_gates[BATCH * AANCH * CDIM];
__device__ __half g_Ahi[2 * NELEM];
__device__ __half g_Alo[2 * NELEM];
__device__ __half g_Whi[NLAYER * CDIM * CDIM];   // [l][n][k]
__device__ __half g_Wlo[NLAYER * CDIM * CDIM];

// ---------------------------------------------------------------------------
__device__ __forceinline__ uint32_t sw128(uint32_t off) {
    return off ^ ((off >> 3) & 0x70);
}
__device__ __forceinline__ void cpa16(uint32_t s, const void* g) {
    asm volatile("cp.async.cg.shared.global [%0], [%1], 16;" :: "r"(s), "l"(g));
}
__device__ __forceinline__ void cpa_commit() {
    asm volatile("cp.async.commit_group;" ::: "memory");
}
__device__ __forceinline__ void cpa_wait1() {
    asm volatile("cp.async.wait_group 1;" ::: "memory");
}
__device__ __forceinline__ void ldsm_x4(uint32_t& r0, uint32_t& r1, uint32_t& r2,
                                        uint32_t& r3, uint32_t a) {
    asm volatile("ldmatrix.sync.aligned.m8n8.x4.shared.b16 {%0,%1,%2,%3}, [%4];"
                 : "=r"(r0), "=r"(r1), "=r"(r2), "=r"(r3) : "r"(a));
}
__device__ __forceinline__ void mma_f16(float* c, const uint32_t* a, const uint32_t* b) {
    asm volatile(
        "mma.sync.aligned.m16n8k16.row.col.f32.f16.f16.f32 "
        "{%0,%1,%2,%3},{%4,%5,%6,%7},{%8,%9},{%0,%1,%2,%3};"
        : "+f"(c[0]), "+f"(c[1]), "+f"(c[2]), "+f"(c[3])
        : "r"(a[0]), "r"(a[1]), "r"(a[2]), "r"(a[3]), "r"(b[0]), "r"(b[1]));
}
__device__ __forceinline__ float gelu_fast(float x) {
    float u = 0.7978845608028654f * fmaf(0.044715f * x, x * x, x);
    float e = __expf(2.0f * u);
    return 0.5f * x * (1.0f + (1.0f - 2.0f / (e + 1.0f)));
}
__device__ __forceinline__ float gelu_tanh(float x) {
    float x3 = x * x * x;
    return 0.5f * x * (1.0f + tanhf(0.7978845608028654f * (x + 0.044715f * x3)));
}
__device__ __forceinline__ uint32_t pack_h2(float a, float b) {
    __half2 t = __floats2half2_rn(a, b);
    return *reinterpret_cast<uint32_t*>(&t);
}
__device__ __forceinline__ __half2 split_hi2(float a, float b, float& la, float& lb) {
    __half ha = __float2half_rn(a);
    __half hb = __float2half_rn(b);
    la = a - __half2float(ha);
    lb = b - __half2float(hb);
    __half2 h; h.x = ha; h.y = hb;
    return h;
}

// ---------------------------------------------------------------------------
// GEMM: 256 thr, 8 warps (4m x 2n), warp tile 32x32, BK=64, 2-stage cp.async,
// per-kk software pipeline: all ldsm issued before the MMA bursts.
// ---------------------------------------------------------------------------
__global__ __launch_bounds__(256, 2)
void gemm_hmma(const __half* __restrict__ aHi, const __half* __restrict__ aLo,
               const __half* __restrict__ bHi, const __half* __restrict__ bLo,
               const float* __restrict__ bias,
               float* __restrict__ out,
               __half* __restrict__ nHi, __half* __restrict__ nLo) {
    extern __shared__ char smraw[];
    const uint32_t sbraw = (uint32_t)__cvta_generic_to_shared(smraw);
    const uint32_t sb = (sbraw + 1023u) & ~1023u;

    const int t = threadIdx.x;
    const int lane = t & 31;
    const int w = t >> 5;
    const int wm = (w >> 1) * 32;
    const int wn = (w & 1) * 32;
    const int bm = blockIdx.x * BM;
    const int bn = blockIdx.y * BN;

    const int a_row = t >> 3;
    const int a_c16 = t & 7;

    auto load_stage = [&](int s, int buf) {
        const int k0 = s * BK;
        const uint32_t stg = sb + (uint32_t)buf * STAGE_BYTES;
#pragma unroll
        for (int p = 0; p < 4; ++p) {
            const int row = p * 32 + a_row;
            const uint32_t so = sw128((uint32_t)row * 128 + a_c16 * 16);
            const size_t gofs = (size_t)(bm + row) * CDIM + k0 + a_c16 * 8;
            cpa16(stg + SA_HI + so, aHi + gofs);
            cpa16(stg + SA_LO + so, aLo + gofs);
        }
#pragma unroll
        for (int p = 0; p < 2; ++p) {
            const int row = p * 32 + a_row;
            const uint32_t so = sw128((uint32_t)row * 128 + a_c16 * 16);
            const size_t gofs = (size_t)(bn + row) * CDIM + k0 + a_c16 * 8;
            cpa16(stg + SB_HI + so, bHi + gofs);
            cpa16(stg + SB_LO + so, bLo + gofs);
        }
    };

    uint32_t a_off[2];
#pragma unroll
    for (int mi = 0; mi < 2; ++mi)
        a_off[mi] = (uint32_t)(wm + mi * 16 + (lane & 15)) * 128 + ((lane >> 4) & 1) * 16;
    uint32_t b_off[2];
#pragma unroll
    for (int g = 0; g < 2; ++g)
        b_off[g] = (uint32_t)(wn + g * 16 + ((lane >> 4) & 1) * 8 + (lane & 7)) * 128 +
                   ((lane >> 3) & 1) * 16;

    float acc[2][4][4];
#pragma unroll
    for (int mi = 0; mi < 2; ++mi)
#pragma unroll
        for (int nf = 0; nf < 4; ++nf)
#pragma unroll
            for (int r = 0; r < 4; ++r) acc[mi][nf][r] = 0.0f;

    load_stage(0, 0); cpa_commit();
    load_stage(1, 1); cpa_commit();

    uint32_t ah[2][4], bh[2][4], ahn[2][4], bhn[2][4], al[2][4], bl[2][4];

#pragma unroll 1
    for (int s = 0; s < KSTAGES; ++s) {
        cpa_wait1();
        __syncthreads();
        const int buf = s & 1;
        const uint32_t stg = sb + (uint32_t)buf * STAGE_BYTES;

        // prime kk=0 hi frags
#pragma unroll
        for (int mi = 0; mi < 2; ++mi)
            ldsm_x4(ah[mi][0], ah[mi][1], ah[mi][2], ah[mi][3],
                    stg + SA_HI + sw128(a_off[mi]));
#pragma unroll
        for (int g = 0; g < 2; ++g)
            ldsm_x4(bh[g][0], bh[g][1], bh[g][2], bh[g][3],
                    stg + SB_HI + sw128(b_off[g]));

#pragma unroll
        for (int kk = 0; kk < 4; ++kk) {
            const uint32_t kb = kk * 32;
            // issue every ldsm this kk needs BEFORE the MMA bursts
#pragma unroll
            for (int mi = 0; mi < 2; ++mi)
                ldsm_x4(al[mi][0], al[mi][1], al[mi][2], al[mi][3],
                        stg + SA_LO + sw128(a_off[mi] + kb));
#pragma unroll
            for (int g = 0; g < 2; ++g)
                ldsm_x4(bl[g][0], bl[g][1], bl[g][2], bl[g][3],
                        stg + SB_LO + sw128(b_off[g] + kb));
            if (kk < 3) {
                const uint32_t kbn = kb + 32;
#pragma unroll
                for (int mi = 0; mi < 2; ++mi)
                    ldsm_x4(ahn[mi][0], ahn[mi][1], ahn[mi][2], ahn[mi][3],
                            stg + SA_HI + sw128(a_off[mi] + kbn));
#pragma unroll
                for (int g = 0; g < 2; ++g)
                    ldsm_x4(bhn[g][0], bhn[g][1], bhn[g][2], bhn[g][3],
                            stg + SB_HI + sw128(b_off[g] + kbn));
            }
            // hi*hi (frags already resident -> covers ldsm latency above)
#pragma unroll
            for (int mi = 0; mi < 2; ++mi)
#pragma unroll
                for (int nf = 0; nf < 4; ++nf)
                    mma_f16(acc[mi][nf], ah[mi], &bh[nf >> 1][(nf & 1) * 2]);
            // lo*hi
#pragma unroll
            for (int mi = 0; mi < 2; ++mi)
#pragma unroll
                for (int nf = 0; nf < 4; ++nf)
                    mma_f16(acc[mi][nf], al[mi], &bh[nf >> 1][(nf & 1) * 2]);
            // hi*lo
#pragma unroll
            for (int mi = 0; mi < 2; ++mi)
#pragma unroll
                for (int nf = 0; nf < 4; ++nf)
                    mma_f16(acc[mi][nf], ah[mi], &bl[nf >> 1][(nf & 1) * 2]);
            // rotate
            if (kk < 3) {
#pragma unroll
                for (int mi = 0; mi < 2; ++mi)
#pragma unroll
                    for (int r = 0; r < 4; ++r) ah[mi][r] = ahn[mi][r];
#pragma unroll
                for (int g = 0; g < 2; ++g)
#pragma unroll
                    for (int r = 0; r < 4; ++r) bh[g][r] = bhn[g][r];
            }
        }
        __syncthreads();
        if (s + 2 < KSTAGES) load_stage(s + 2, buf);
        cpa_commit();
    }

    // epilogue
    const int r0 = bm + wm + (lane >> 2);
    const int cbase = bn + wn + (lane & 3) * 2;
#pragma unroll
    for (int mi = 0; mi < 2; ++mi) {
#pragma unroll
        for (int nf = 0; nf < 4; ++nf) {
            const int c = cbase + nf * 8;
            const float2 bv = *reinterpret_cast<const float2*>(&bias[c]);
            const int ra = r0 + mi * 16;
            const int rb = ra + 8;
            float v0 = gelu_fast(acc[mi][nf][0] + bv.x);
            float v1 = gelu_fast(acc[mi][nf][1] + bv.y);
            float v2 = gelu_fast(acc[mi][nf][2] + bv.x);
            float v3 = gelu_fast(acc[mi][nf][3] + bv.y);
            if (out) {
                *reinterpret_cast<float2*>(&out[(size_t)ra * CDIM + c]) = make_float2(v0, v1);
                *reinterpret_cast<float2*>(&out[(size_t)rb * CDIM + c]) = make_float2(v2, v3);
            }
            if (nHi) {
                float l0, l1, l2, l3;
                __half2 h01 = split_hi2(v0, v1, l0, l1);
                __half2 h23 = split_hi2(v2, v3, l2, l3);
                *reinterpret_cast<__half2*>(&nHi[(size_t)ra * CDIM + c]) = h01;
                *reinterpret_cast<__half2*>(&nHi[(size_t)rb * CDIM + c]) = h23;
                *reinterpret_cast<uint32_t*>(&nLo[(size_t)ra * CDIM + c]) = pack_h2(l0, l1);
                *reinterpret_cast<uint32_t*>(&nLo[(size_t)rb * CDIM + c]) = pack_h2(l2, l3);
            }
        }
    }
}

// ---------------------------------------------------------------------------
__global__ void convert_x(const float* __restrict__ x,
                          __half* __restrict__ hi, __half* __restrict__ lo) {
    int i = blockIdx.x * blockDim.x + threadIdx.x;
    if (i >= NELEM / 4) return;
    float4 v = reinterpret_cast<const float4*>(x)[i];
    float l0, l1, l2, l3;
    __half2 h01 = split_hi2(v.x, v.y, l0, l1);
    __half2 h23 = split_hi2(v.z, v.w, l2, l3);
    reinterpret_cast<uint2*>(hi)[i] = make_uint2(*reinterpret_cast<uint32_t*>(&h01),
                                                 *reinterpret_cast<uint32_t*>(&h23));
    reinterpret_cast<uint2*>(lo)[i] = make_uint2(pack_h2(l0, l1), pack_h2(l2, l3));
}

__global__ void convert_w(const float* __restrict__ W,
                          __half* __restrict__ whi, __half* __restrict__ wlo) {
    __shared__ float tile[32][33];
    const int l = blockIdx.z;
    const int kt = blockIdx.y * 32;
    const int nt = blockIdx.x * 32;
    const int tx = threadIdx.x, ty = threadIdx.y;
    const size_t lb = (size_t)l * CDIM * CDIM;
#pragma unroll
    for (int q = 0; q < 4; ++q)
        tile[ty + 8 * q][tx] = W[lb + (size_t)(kt + ty + 8 * q) * CDIM + nt + tx];
    __syncthreads();
#pragma unroll
    for (int q = 0; q < 4; ++q) {
        float v = tile[tx][ty + 8 * q];
        __half h = __float2half_rn(v);
        size_t idx = lb + (size_t)(nt + ty + 8 * q) * CDIM + kt + tx;
        whi[idx] = h;
        wlo[idx] = __float2half_rn(v - __half2float(h));
    }
}

// ---------------------------------------------------------------------------
__global__ __launch_bounds__(128)
void gate_kernel(const float* __restrict__ act,
                 const float* __restrict__ fc1w, const float* __restrict__ fc1b,
                 const float* __restrict__ fc2w, const float* __restrict__ fc2b,
                 float* __restrict__ gates) {
    __shared__ float ps[CDIM];
    __shared__ float hs[HIDN];
    __shared__ float lg[AANCH * CDIM];
    const int b = blockIdx.x;
    const int t = threadIdx.x;

    {
        const float* p = act + (size_t)b * HW * CDIM + t * 4;
        float4 s = make_float4(0.f, 0.f, 0.f, 0.f);
#pragma unroll 4
        for (int r = 0; r < HW; ++r) {
            float4 v = *reinterpret_cast<const float4*>(p + (size_t)r * CDIM);
            s.x += v.x; s.y += v.y; s.z += v.z; s.w += v.w;
        }
        const float inv = 1.0f / (float)HW;
        *reinterpret_cast<float4*>(&ps[t * 4]) =
            make_float4(s.x * inv, s.y * inv, s.z * inv, s.w * inv);
    }
    __syncthreads();

    float acc = fc1b[t];
#pragma unroll 8
    for (int k = 0; k < CDIM; ++k)
        acc = fmaf(ps[k], fc1w[k * HIDN + t], acc);
    hs[t] = gelu_tanh(acc);
    __syncthreads();

    for (int j = t; j < AANCH * CDIM; j += 128) {
        float a2 = fc2b[j];
#pragma unroll 8
        for (int k = 0; k < HIDN; ++k)
            a2 = fmaf(hs[k], fc2w[k * (AANCH * CDIM) + j], a2);
        lg[j] = a2;
    }
    __syncthreads();

    for (int c = t; c < CDIM; c += 128) {
        float l0 = lg[c], l1 = lg[CDIM + c], l2 = lg[2 * CDIM + c];
        float m = fmaxf(l0, fmaxf(l1, l2));
        float e0 = expf(l0 - m), e1 = expf(l1 - m), e2 = expf(l2 - m);
        float inv = 1.0f / (e0 + e1 + e2);
        gates[b * AANCH * CDIM + c]            = e0 * inv;
        gates[b * AANCH * CDIM + CDIM + c]     = e1 * inv;
        gates[b * AANCH * CDIM + 2 * CDIM + c] = e2 * inv;
    }
}

__global__ void route_kernel(float* __restrict__ nx,
                             const float* __restrict__ a0,
                             const float* __restrict__ a1,
                             const float* __restrict__ a2,
                             const float* __restrict__ gates,
                             const float* __restrict__ gammas, int tgt,
                             __half* __restrict__ nhi,
                             __half* __restrict__ nlo) {
    const int i = blockIdx.x * blockDim.x + threadIdx.x;
    if (i >= NELEM / 4) return;
    const float gamma = gammas[tgt];
    const int per_b = HW * CDIM / 4;
    const int b = i / per_b;
    const int c4 = i & (CDIM / 4 - 1);

    const float4 g0 = *reinterpret_cast<const float4*>(&gates[b * AANCH * CDIM + c4 * 4]);
    const float4 g1 = *reinterpret_cast<const float4*>(&gates[b * AANCH * CDIM + CDIM + c4 * 4]);
    const float4 g2 = *reinterpret_cast<const float4*>(&gates[b * AANCH * CDIM + 2 * CDIM + c4 * 4]);

    float4 v  = reinterpret_cast<float4*>(nx)[i];
    float4 x0 = reinterpret_cast<const float4*>(a0)[i];
    float4 x1 = reinterpret_cast<const float4*>(a1)[i];
    float4 x2 = reinterpret_cast<const float4*>(a2)[i];

    v.x += gamma * (g0.x * x0.x + g1.x * x1.x + g2.x * x2.x);
    v.y += gamma * (g0.y * x0.y + g1.y * x1.y + g2.y * x2.y);
    v.z += gamma * (g0.z * x0.z + g1.z * x1.z + g2.z * x2.z);
    v.w += gamma * (g0.w * x0.w + g1.w * x1.w + g2.w * x2.w);

    reinterpret_cast<float4*>(nx)[i] = v;

    if (nhi) {
        float l0, l1, l2, l3;
        __half2 h01 = split_hi2(v.x, v.y, l0, l1);
        __half2 h23 = split_hi2(v.z, v.w, l2, l3);
        reinterpret_cast<uint2*>(nhi)[i] = make_uint2(*reinterpret_cast<uint32_t*>(&h01),
                                                      *reinterpret_cast<uint32_t*>(&h23));
        reinterpret_cast<uint2*>(nlo)[i] = make_uint2(pack_h2(l0, l1), pack_h2(l2, l3));
    }
}

// ---------------------------------------------------------------------------
extern "C" void kernel_launch(void* const* d_in, const int* in_sizes, int n_in,
                              void* d_out, int out_size) {
    const float* x   = (const float*)d_in[0];
    const float* bw  = (const float*)d_in[1];
    const float* bb  = (const float*)d_in[2];
    const float* f1w = (const float*)d_in[3];
    const float* f1b = (const float*)d_in[4];
    const float* f2w = (const float*)d_in[5];
    const float* f2b = (const float*)d_in[6];
    const float* gam = (const float*)d_in[7];

    float *bufA, *anc0, *anc1, *anc2, *gates;
    __half *ahi, *alo, *whi, *wlo;
    cudaGetSymbolAddress((void**)&bufA,  g_bufA);
    cudaGetSymbolAddress((void**)&anc0,  g_anc0);
    cudaGetSymbolAddress((void**)&anc1,  g_anc1);
    cudaGetSymbolAddress((void**)&anc2,  g_anc2);
    cudaGetSymbolAddress((void**)&gates, g_gates);
    cudaGetSymbolAddress((void**)&ahi,   g_Ahi);
    cudaGetSymbolAddress((void**)&alo,   g_Alo);
    cudaGetSymbolAddress((void**)&whi,   g_Whi);
    cudaGetSymbolAddress((void**)&wlo,   g_Wlo);

    cudaFuncSetAttribute(gemm_hmma, cudaFuncAttributeMaxDynamicSharedMemorySize, SMEM_DYN);

    convert_w<<<dim3(CDIM / 32, CDIM / 32, NLAYER), dim3(32, 8)>>>(bw, whi, wlo);
    convert_x<<<(NELEM / 4 + 255) / 256, 256>>>(x, ahi, alo);

    const dim3 gemm_grid(M_TOT / BM, CDIM / BN);   // 49 x 8
    int tcount = 0;
    for (int i = 0; i < NLAYER; ++i) {
        float* dst;
        if      (i == 1)  dst = anc0;
        else if (i == 4)  dst = anc1;
        else if (i == 9)  dst = anc2;
        else if (i == 17) dst = (float*)d_out;
        else if (i == 11 || i == 14) dst = bufA;
        else              dst = nullptr;

        const int inS  = i & 1;
        const int outS = (i + 1) & 1;
        const bool last = (i == 17);
        __half* nhi = last ? nullptr : ahi + (size_t)outS * NELEM;
        __half* nlo = last ? nullptr : alo + (size_t)outS * NELEM;

        gemm_hmma<<<gemm_grid, 256, SMEM_DYN>>>(
            ahi + (size_t)inS * NELEM, alo + (size_t)inS * NELEM,
            whi + (size_t)i * CDIM * CDIM, wlo + (size_t)i * CDIM * CDIM,
            bb + (size_t)i * CDIM, dst, nhi, nlo);

        if (i == 11 || i == 14 || i == 17) {
            const int tt = tcount++;
            gate_kernel<<<BATCH, 128>>>(dst,
                                        f1w + (size_t)tt * CDIM * HIDN,
                                        f1b + (size_t)tt * HIDN,
                                        f2w + (size_t)tt * HIDN * AANCH * CDIM,
                                        f2b + (size_t)tt * AANCH * CDIM,
                                        gates);
            route_kernel<<<(NELEM / 4 + 255) / 256, 256>>>(dst, anc0, anc1, anc2,
                                                           gates, gam, tt, nhi, nlo);
        }
    }
}

// round 7
// speedup vs baseline: 1.0796x; 1.0139x over previous
#include <cuda_runtime.h>
#include <cuda_fp16.h>
#include <cstdint>
#include <math.h>

// ---------------------------------------------------------------------------
// Round 7: R6 GEMM (best) + PDL (programmatic dependent launch) on all nodes
// to eliminate inter-kernel launch gaps in the captured graph.
// ---------------------------------------------------------------------------

#define M_TOT   6272
#define CDIM    512
#define HW      196
#define BATCH   32
#define HIDN    128
#define AANCH   3
#define NELEM   (M_TOT * CDIM)
#define NLAYER  18

#define BM 128
#define BN 64
#define BK 64
#define KSTAGES 8
#define SA_HI 0
#define SA_LO 16384
#define SB_HI 32768
#define SB_LO 40960
#define STAGE_BYTES 49152
#define SMEM_DYN (1024 + 2 * STAGE_BYTES)

__device__ float g_bufA[NELEM];
__device__ float g_anc0[NELEM];
__device__ float g_anc1[NELEM];
__device__ float g_anc2[NELEM];
__device__ float g_gates[BATCH * AANCH * CDIM];
__device__ __half g_Ahi[2 * NELEM];
__device__ __half g_Alo[2 * NELEM];
__device__ __half g_Whi[NLAYER * CDIM * CDIM];   // [l][n][k]
__device__ __half g_Wlo[NLAYER * CDIM * CDIM];

// ---------------------------------------------------------------------------
__device__ __forceinline__ void gdc_wait() {
    asm volatile("griddepcontrol.wait;" ::: "memory");
}
__device__ __forceinline__ uint32_t sw128(uint32_t off) {
    return off ^ ((off >> 3) & 0x70);
}
__device__ __forceinline__ void cpa16(uint32_t s, const void* g) {
    asm volatile("cp.async.cg.shared.global [%0], [%1], 16;" :: "r"(s), "l"(g));
}
__device__ __forceinline__ void cpa_commit() {
    asm volatile("cp.async.commit_group;" ::: "memory");
}
__device__ __forceinline__ void cpa_wait1() {
    asm volatile("cp.async.wait_group 1;" ::: "memory");
}
__device__ __forceinline__ void ldsm_x4(uint32_t& r0, uint32_t& r1, uint32_t& r2,
                                        uint32_t& r3, uint32_t a) {
    asm volatile("ldmatrix.sync.aligned.m8n8.x4.shared.b16 {%0,%1,%2,%3}, [%4];"
                 : "=r"(r0), "=r"(r1), "=r"(r2), "=r"(r3) : "r"(a));
}
__device__ __forceinline__ void mma_f16(float* c, const uint32_t* a, const uint32_t* b) {
    asm volatile(
        "mma.sync.aligned.m16n8k16.row.col.f32.f16.f16.f32 "
        "{%0,%1,%2,%3},{%4,%5,%6,%7},{%8,%9},{%0,%1,%2,%3};"
        : "+f"(c[0]), "+f"(c[1]), "+f"(c[2]), "+f"(c[3])
        : "r"(a[0]), "r"(a[1]), "r"(a[2]), "r"(a[3]), "r"(b[0]), "r"(b[1]));
}
__device__ __forceinline__ float gelu_fast(float x) {
    float u = 0.7978845608028654f * fmaf(0.044715f * x, x * x, x);
    float e = __expf(2.0f * u);
    return 0.5f * x * (1.0f + (1.0f - 2.0f / (e + 1.0f)));
}
__device__ __forceinline__ float gelu_tanh(float x) {
    float x3 = x * x * x;
    return 0.5f * x * (1.0f + tanhf(0.7978845608028654f * (x + 0.044715f * x3)));
}
__device__ __forceinline__ uint32_t pack_h2(float a, float b) {
    __half2 t = __floats2half2_rn(a, b);
    return *reinterpret_cast<uint32_t*>(&t);
}
__device__ __forceinline__ __half2 split_hi2(float a, float b, float& la, float& lb) {
    __half ha = __float2half_rn(a);
    __half hb = __float2half_rn(b);
    la = a - __half2float(ha);
    lb = b - __half2float(hb);
    __half2 h; h.x = ha; h.y = hb;
    return h;
}

// ---------------------------------------------------------------------------
// GEMM (identical structure to R6 best)
// ---------------------------------------------------------------------------
__global__ __launch_bounds__(256, 2)
void gemm_hmma(const __half* __restrict__ aHi, const __half* __restrict__ aLo,
               const __half* __restrict__ bHi, const __half* __restrict__ bLo,
               const float* __restrict__ bias,
               float* __restrict__ out,
               __half* __restrict__ nHi, __half* __restrict__ nLo) {
    gdc_wait();
    extern __shared__ char smraw[];
    const uint32_t sbraw = (uint32_t)__cvta_generic_to_shared(smraw);
    const uint32_t sb = (sbraw + 1023u) & ~1023u;

    const int t = threadIdx.x;
    const int lane = t & 31;
    const int w = t >> 5;
    const int wm = (w >> 1) * 32;
    const int wn = (w & 1) * 32;
    const int bm = blockIdx.x * BM;
    const int bn = blockIdx.y * BN;

    const int a_row = t >> 3;
    const int a_c16 = t & 7;

    auto load_stage = [&](int s, int buf) {
        const int k0 = s * BK;
        const uint32_t stg = sb + (uint32_t)buf * STAGE_BYTES;
#pragma unroll
        for (int p = 0; p < 4; ++p) {
            const int row = p * 32 + a_row;
            const uint32_t so = sw128((uint32_t)row * 128 + a_c16 * 16);
            const size_t gofs = (size_t)(bm + row) * CDIM + k0 + a_c16 * 8;
            cpa16(stg + SA_HI + so, aHi + gofs);
            cpa16(stg + SA_LO + so, aLo + gofs);
        }
#pragma unroll
        for (int p = 0; p < 2; ++p) {
            const int row = p * 32 + a_row;
            const uint32_t so = sw128((uint32_t)row * 128 + a_c16 * 16);
            const size_t gofs = (size_t)(bn + row) * CDIM + k0 + a_c16 * 8;
            cpa16(stg + SB_HI + so, bHi + gofs);
            cpa16(stg + SB_LO + so, bLo + gofs);
        }
    };

    uint32_t a_off[2];
#pragma unroll
    for (int mi = 0; mi < 2; ++mi)
        a_off[mi] = (uint32_t)(wm + mi * 16 + (lane & 15)) * 128 + ((lane >> 4) & 1) * 16;
    uint32_t b_off[2];
#pragma unroll
    for (int g = 0; g < 2; ++g)
        b_off[g] = (uint32_t)(wn + g * 16 + ((lane >> 4) & 1) * 8 + (lane & 7)) * 128 +
                   ((lane >> 3) & 1) * 16;

    float acc[2][4][4];
#pragma unroll
    for (int mi = 0; mi < 2; ++mi)
#pragma unroll
        for (int nf = 0; nf < 4; ++nf)
#pragma unroll
            for (int r = 0; r < 4; ++r) acc[mi][nf][r] = 0.0f;

    load_stage(0, 0); cpa_commit();
    load_stage(1, 1); cpa_commit();

    uint32_t ah[2][4], bh[2][4], ahn[2][4], bhn[2][4], al[2][4], bl[2][4];

#pragma unroll 1
    for (int s = 0; s < KSTAGES; ++s) {
        cpa_wait1();
        __syncthreads();
        const int buf = s & 1;
        const uint32_t stg = sb + (uint32_t)buf * STAGE_BYTES;

#pragma unroll
        for (int mi = 0; mi < 2; ++mi)
            ldsm_x4(ah[mi][0], ah[mi][1], ah[mi][2], ah[mi][3],
                    stg + SA_HI + sw128(a_off[mi]));
#pragma unroll
        for (int g = 0; g < 2; ++g)
            ldsm_x4(bh[g][0], bh[g][1], bh[g][2], bh[g][3],
                    stg + SB_HI + sw128(b_off[g]));

#pragma unroll
        for (int kk = 0; kk < 4; ++kk) {
            const uint32_t kb = kk * 32;
#pragma unroll
            for (int mi = 0; mi < 2; ++mi)
                ldsm_x4(al[mi][0], al[mi][1], al[mi][2], al[mi][3],
                        stg + SA_LO + sw128(a_off[mi] + kb));
#pragma unroll
            for (int g = 0; g < 2; ++g)
                ldsm_x4(bl[g][0], bl[g][1], bl[g][2], bl[g][3],
                        stg + SB_LO + sw128(b_off[g] + kb));
            if (kk < 3) {
                const uint32_t kbn = kb + 32;
#pragma unroll
                for (int mi = 0; mi < 2; ++mi)
                    ldsm_x4(ahn[mi][0], ahn[mi][1], ahn[mi][2], ahn[mi][3],
                            stg + SA_HI + sw128(a_off[mi] + kbn));
#pragma unroll
                for (int g = 0; g < 2; ++g)
                    ldsm_x4(bhn[g][0], bhn[g][1], bhn[g][2], bhn[g][3],
                            stg + SB_HI + sw128(b_off[g] + kbn));
            }
#pragma unroll
            for (int mi = 0; mi < 2; ++mi)
#pragma unroll
                for (int nf = 0; nf < 4; ++nf)
                    mma_f16(acc[mi][nf], ah[mi], &bh[nf >> 1][(nf & 1) * 2]);
#pragma unroll
            for (int mi = 0; mi < 2; ++mi)
#pragma unroll
                for (int nf = 0; nf < 4; ++nf)
                    mma_f16(acc[mi][nf], al[mi], &bh[nf >> 1][(nf & 1) * 2]);
#pragma unroll
            for (int mi = 0; mi < 2; ++mi)
#pragma unroll
                for (int nf = 0; nf < 4; ++nf)
                    mma_f16(acc[mi][nf], ah[mi], &bl[nf >> 1][(nf & 1) * 2]);
            if (kk < 3) {
#pragma unroll
                for (int mi = 0; mi < 2; ++mi)
#pragma unroll
                    for (int r = 0; r < 4; ++r) ah[mi][r] = ahn[mi][r];
#pragma unroll
                for (int g = 0; g < 2; ++g)
#pragma unroll
                    for (int r = 0; r < 4; ++r) bh[g][r] = bhn[g][r];
            }
        }
        __syncthreads();
        if (s + 2 < KSTAGES) load_stage(s + 2, buf);
        cpa_commit();
    }

    const int r0 = bm + wm + (lane >> 2);
    const int cbase = bn + wn + (lane & 3) * 2;
#pragma unroll
    for (int mi = 0; mi < 2; ++mi) {
#pragma unroll
        for (int nf = 0; nf < 4; ++nf) {
            const int c = cbase + nf * 8;
            const float2 bv = *reinterpret_cast<const float2*>(&bias[c]);
            const int ra = r0 + mi * 16;
            const int rb = ra + 8;
            float v0 = gelu_fast(acc[mi][nf][0] + bv.x);
            float v1 = gelu_fast(acc[mi][nf][1] + bv.y);
            float v2 = gelu_fast(acc[mi][nf][2] + bv.x);
            float v3 = gelu_fast(acc[mi][nf][3] + bv.y);
            if (out) {
                *reinterpret_cast<float2*>(&out[(size_t)ra * CDIM + c]) = make_float2(v0, v1);
                *reinterpret_cast<float2*>(&out[(size_t)rb * CDIM + c]) = make_float2(v2, v3);
            }
            if (nHi) {
                float l0, l1, l2, l3;
                __half2 h01 = split_hi2(v0, v1, l0, l1);
                __half2 h23 = split_hi2(v2, v3, l2, l3);
                *reinterpret_cast<__half2*>(&nHi[(size_t)ra * CDIM + c]) = h01;
                *reinterpret_cast<__half2*>(&nHi[(size_t)rb * CDIM + c]) = h23;
                *reinterpret_cast<uint32_t*>(&nLo[(size_t)ra * CDIM + c]) = pack_h2(l0, l1);
                *reinterpret_cast<uint32_t*>(&nLo[(size_t)rb * CDIM + c]) = pack_h2(l2, l3);
            }
        }
    }
}

// ---------------------------------------------------------------------------
__global__ void convert_x(const float* __restrict__ x,
                          __half* __restrict__ hi, __half* __restrict__ lo) {
    gdc_wait();
    int i = blockIdx.x * blockDim.x + threadIdx.x;
    if (i >= NELEM / 4) return;
    float4 v = reinterpret_cast<const float4*>(x)[i];
    float l0, l1, l2, l3;
    __half2 h01 = split_hi2(v.x, v.y, l0, l1);
    __half2 h23 = split_hi2(v.z, v.w, l2, l3);
    reinterpret_cast<uint2*>(hi)[i] = make_uint2(*reinterpret_cast<uint32_t*>(&h01),
                                                 *reinterpret_cast<uint32_t*>(&h23));
    reinterpret_cast<uint2*>(lo)[i] = make_uint2(pack_h2(l0, l1), pack_h2(l2, l3));
}

__global__ void convert_w(const float* __restrict__ W,
                          __half* __restrict__ whi, __half* __restrict__ wlo) {
    gdc_wait();
    __shared__ float tile[32][33];
    const int l = blockIdx.z;
    const int kt = blockIdx.y * 32;
    const int nt = blockIdx.x * 32;
    const int tx = threadIdx.x, ty = threadIdx.y;
    const size_t lb = (size_t)l * CDIM * CDIM;
#pragma unroll
    for (int q = 0; q < 4; ++q)
        tile[ty + 8 * q][tx] = W[lb + (size_t)(kt + ty + 8 * q) * CDIM + nt + tx];
    __syncthreads();
#pragma unroll
    for (int q = 0; q < 4; ++q) {
        float v = tile[tx][ty + 8 * q];
        __half h = __float2half_rn(v);
        size_t idx = lb + (size_t)(nt + ty + 8 * q) * CDIM + kt + tx;
        whi[idx] = h;
        wlo[idx] = __float2half_rn(v - __half2float(h));
    }
}

// ---------------------------------------------------------------------------
__global__ __launch_bounds__(128)
void gate_kernel(const float* __restrict__ act,
                 const float* __restrict__ fc1w, const float* __restrict__ fc1b,
                 const float* __restrict__ fc2w, const float* __restrict__ fc2b,
                 float* __restrict__ gates) {
    gdc_wait();
    __shared__ float ps[CDIM];
    __shared__ float hs[HIDN];
    __shared__ float lg[AANCH * CDIM];
    const int b = blockIdx.x;
    const int t = threadIdx.x;

    {
        const float* p = act + (size_t)b * HW * CDIM + t * 4;
        float4 s = make_float4(0.f, 0.f, 0.f, 0.f);
#pragma unroll 4
        for (int r = 0; r < HW; ++r) {
            float4 v = *reinterpret_cast<const float4*>(p + (size_t)r * CDIM);
            s.x += v.x; s.y += v.y; s.z += v.z; s.w += v.w;
        }
        const float inv = 1.0f / (float)HW;
        *reinterpret_cast<float4*>(&ps[t * 4]) =
            make_float4(s.x * inv, s.y * inv, s.z * inv, s.w * inv);
    }
    __syncthreads();

    float acc = fc1b[t];
#pragma unroll 8
    for (int k = 0; k < CDIM; ++k)
        acc = fmaf(ps[k], fc1w[k * HIDN + t], acc);
    hs[t] = gelu_tanh(acc);
    __syncthreads();

    for (int j = t; j < AANCH * CDIM; j += 128) {
        float a2 = fc2b[j];
#pragma unroll 8
        for (int k = 0; k < HIDN; ++k)
            a2 = fmaf(hs[k], fc2w[k * (AANCH * CDIM) + j], a2);
        lg[j] = a2;
    }
    __syncthreads();

    for (int c = t; c < CDIM; c += 128) {
        float l0 = lg[c], l1 = lg[CDIM + c], l2 = lg[2 * CDIM + c];
        float m = fmaxf(l0, fmaxf(l1, l2));
        float e0 = expf(l0 - m), e1 = expf(l1 - m), e2 = expf(l2 - m);
        float inv = 1.0f / (e0 + e1 + e2);
        gates[b * AANCH * CDIM + c]            = e0 * inv;
        gates[b * AANCH * CDIM + CDIM + c]     = e1 * inv;
        gates[b * AANCH * CDIM + 2 * CDIM + c] = e2 * inv;
    }
}

__global__ void route_kernel(float* __restrict__ nx,
                             const float* __restrict__ a0,
                             const float* __restrict__ a1,
                             const float* __restrict__ a2,
                             const float* __restrict__ gates,
                             const float* __restrict__ gammas, int tgt,
                             __half* __restrict__ nhi,
                             __half* __restrict__ nlo) {
    gdc_wait();
    const int i = blockIdx.x * blockDim.x + threadIdx.x;
    if (i >= NELEM / 4) return;
    const float gamma = gammas[tgt];
    const int per_b = HW * CDIM / 4;
    const int b = i / per_b;
    const int c4 = i & (CDIM / 4 - 1);

    const float4 g0 = *reinterpret_cast<const float4*>(&gates[b * AANCH * CDIM + c4 * 4]);
    const float4 g1 = *reinterpret_cast<const float4*>(&gates[b * AANCH * CDIM + CDIM + c4 * 4]);
    const float4 g2 = *reinterpret_cast<const float4*>(&gates[b * AANCH * CDIM + 2 * CDIM + c4 * 4]);

    float4 v  = reinterpret_cast<float4*>(nx)[i];
    float4 x0 = reinterpret_cast<const float4*>(a0)[i];
    float4 x1 = reinterpret_cast<const float4*>(a1)[i];
    float4 x2 = reinterpret_cast<const float4*>(a2)[i];

    v.x += gamma * (g0.x * x0.x + g1.x * x1.x + g2.x * x2.x);
    v.y += gamma * (g0.y * x0.y + g1.y * x1.y + g2.y * x2.y);
    v.z += gamma * (g0.z * x0.z + g1.z * x1.z + g2.z * x2.z);
    v.w += gamma * (g0.w * x0.w + g1.w * x1.w + g2.w * x2.w);

    reinterpret_cast<float4*>(nx)[i] = v;

    if (nhi) {
        float l0, l1, l2, l3;
        __half2 h01 = split_hi2(v.x, v.y, l0, l1);
        __half2 h23 = split_hi2(v.z, v.w, l2, l3);
        reinterpret_cast<uint2*>(nhi)[i] = make_uint2(*reinterpret_cast<uint32_t*>(&h01),
                                                      *reinterpret_cast<uint32_t*>(&h23));
        reinterpret_cast<uint2*>(nlo)[i] = make_uint2(pack_h2(l0, l1), pack_h2(l2, l3));
    }
}

// ---------------------------------------------------------------------------
// PDL launch helper: programmatic stream serialization; fallback = plain.
// ---------------------------------------------------------------------------
template <typename K, typename... Args>
static inline void launch_pdl(K k, dim3 g, dim3 b, size_t smem, Args... args) {
    cudaLaunchConfig_t cfg = {};
    cfg.gridDim = g;
    cfg.blockDim = b;
    cfg.dynamicSmemBytes = smem;
    cfg.stream = 0;
    cudaLaunchAttribute at[1];
    at[0].id = cudaLaunchAttributeProgrammaticStreamSerialization;
    at[0].val.programmaticStreamSerializationAllowed = 1;
    cfg.attrs = at;
    cfg.numAttrs = 1;
    if (cudaLaunchKernelEx(&cfg, k, args...) != cudaSuccess) {
        k<<<g, b, smem>>>(args...);
    }
}

extern "C" void kernel_launch(void* const* d_in, const int* in_sizes, int n_in,
                              void* d_out, int out_size) {
    const float* x   = (const float*)d_in[0];
    const float* bw  = (const float*)d_in[1];
    const float* bb  = (const float*)d_in[2];
    const float* f1w = (const float*)d_in[3];
    const float* f1b = (const float*)d_in[4];
    const float* f2w = (const float*)d_in[5];
    const float* f2b = (const float*)d_in[6];
    const float* gam = (const float*)d_in[7];

    float *bufA, *anc0, *anc1, *anc2, *gates;
    __half *ahi, *alo, *whi, *wlo;
    cudaGetSymbolAddress((void**)&bufA,  g_bufA);
    cudaGetSymbolAddress((void**)&anc0,  g_anc0);
    cudaGetSymbolAddress((void**)&anc1,  g_anc1);
    cudaGetSymbolAddress((void**)&anc2,  g_anc2);
    cudaGetSymbolAddress((void**)&gates, g_gates);
    cudaGetSymbolAddress((void**)&ahi,   g_Ahi);
    cudaGetSymbolAddress((void**)&alo,   g_Alo);
    cudaGetSymbolAddress((void**)&whi,   g_Whi);
    cudaGetSymbolAddress((void**)&wlo,   g_Wlo);

    cudaFuncSetAttribute(gemm_hmma, cudaFuncAttributeMaxDynamicSharedMemorySize, SMEM_DYN);

    launch_pdl(convert_w, dim3(CDIM / 32, CDIM / 32, NLAYER), dim3(32, 8), 0,
               bw, whi, wlo);
    launch_pdl(convert_x, dim3((NELEM / 4 + 255) / 256), dim3(256), 0,
               x, ahi, alo);

    const dim3 gemm_grid(M_TOT / BM, CDIM / BN);   // 49 x 8
    int tcount = 0;
    for (int i = 0; i < NLAYER; ++i) {
        float* dst;
        if      (i == 1)  dst = anc0;
        else if (i == 4)  dst = anc1;
        else if (i == 9)  dst = anc2;
        else if (i == 17) dst = (float*)d_out;
        else if (i == 11 || i == 14) dst = bufA;
        else              dst = nullptr;

        const int inS  = i & 1;
        const int outS = (i + 1) & 1;
        const bool last = (i == 17);
        __half* nhi = last ? nullptr : ahi + (size_t)outS * NELEM;
        __half* nlo = last ? nullptr : alo + (size_t)outS * NELEM;

        launch_pdl(gemm_hmma, gemm_grid, dim3(256), (size_t)SMEM_DYN,
                   (const __half*)(ahi + (size_t)inS * NELEM),
                   (const __half*)(alo + (size_t)inS * NELEM),
                   (const __half*)(whi + (size_t)i * CDIM * CDIM),
                   (const __half*)(wlo + (size_t)i * CDIM * CDIM),
                   (const float*)(bb + (size_t)i * CDIM),
                   dst, nhi, nlo);

        if (i == 11 || i == 14 || i == 17) {
            const int tt = tcount++;
            launch_pdl(gate_kernel, dim3(BATCH), dim3(128), 0,
                       (const float*)dst,
                       (const float*)(f1w + (size_t)tt * CDIM * HIDN),
                       (const float*)(f1b + (size_t)tt * HIDN),
                       (const float*)(f2w + (size_t)tt * HIDN * AANCH * CDIM),
                       (const float*)(f2b + (size_t)tt * AANCH * CDIM),
                       gates);
            launch_pdl(route_kernel, dim3((NELEM / 4 + 255) / 256), dim3(256), 0,
                       dst, (const float*)anc0, (const float*)anc1, (const float*)anc2,
                       (const float*)gates, gam, tt, nhi, nlo);
        }
    }
}

// round 8
// speedup vs baseline: 1.2054x; 1.1165x over previous
#include <cuda_runtime.h>
#include <cuda_fp16.h>
#include <cstdint>
#include <math.h>

// ---------------------------------------------------------------------------
// Round 8: persistent megakernel — 18 HMMA split-fp16 GEMM layers + gating in
// ONE kernel with global-atomic grid barriers. 296 CTAs (2/SM), work striped.
// Cross-layer reads bypass L1 (cp.async.cg / __ldcg) since L1 isn't coherent
// across SMs within a kernel.
// ---------------------------------------------------------------------------

#define M_TOT   6272
#define CDIM    512
#define HW      196
#define BATCH   32
#define HIDN    128
#define AANCH   3
#define NELEM   (M_TOT * CDIM)
#define NLAYER  18

#define BM 128
#define BN 64
#define BK 64
#define KSTAGES 8
#define SA_HI 0
#define SA_LO 16384
#define SB_HI 32768
#define SB_LO 40960
#define STAGE_BYTES 49152
#define SMEM_DYN (1024 + 2 * STAGE_BYTES)

#define NCTA 296                 // 2 per SM x 148
#define NTILE 392                // 49 x 8

__device__ float g_bufA[NELEM];
__device__ float g_anc0[NELEM];
__device__ float g_anc1[NELEM];
__device__ float g_anc2[NELEM];
__device__ float g_gates[BATCH * AANCH * CDIM];
__device__ __half g_Ahi[2 * NELEM];
__device__ __half g_Alo[2 * NELEM];
__device__ __half g_Whi[NLAYER * CDIM * CDIM];   // [l][n][k]
__device__ __half g_Wlo[NLAYER * CDIM * CDIM];
__device__ unsigned g_bar_cnt = 0;
__device__ unsigned g_bar_gen = 0;

// ---------------------------------------------------------------------------
__device__ __forceinline__ void grid_sync() {
    __syncthreads();
    if (threadIdx.x == 0) {
        __threadfence();
        unsigned gen = *((volatile unsigned*)&g_bar_gen);
        if (atomicAdd(&g_bar_cnt, 1u) == NCTA - 1u) {
            g_bar_cnt = 0;
            __threadfence();
            atomicAdd(&g_bar_gen, 1u);
        } else {
            while (*((volatile unsigned*)&g_bar_gen) == gen) {}
        }
    }
    __syncthreads();
}
__device__ __forceinline__ uint32_t sw128(uint32_t off) {
    return off ^ ((off >> 3) & 0x70);
}
__device__ __forceinline__ void cpa16(uint32_t s, const void* g) {
    asm volatile("cp.async.cg.shared.global [%0], [%1], 16;" :: "r"(s), "l"(g));
}
__device__ __forceinline__ void cpa_commit() {
    asm volatile("cp.async.commit_group;" ::: "memory");
}
__device__ __forceinline__ void cpa_wait1() {
    asm volatile("cp.async.wait_group 1;" ::: "memory");
}
__device__ __forceinline__ void ldsm_x4(uint32_t& r0, uint32_t& r1, uint32_t& r2,
                                        uint32_t& r3, uint32_t a) {
    asm volatile("ldmatrix.sync.aligned.m8n8.x4.shared.b16 {%0,%1,%2,%3}, [%4];"
                 : "=r"(r0), "=r"(r1), "=r"(r2), "=r"(r3) : "r"(a));
}
__device__ __forceinline__ void mma_f16(float* c, const uint32_t* a, const uint32_t* b) {
    asm volatile(
        "mma.sync.aligned.m16n8k16.row.col.f32.f16.f16.f32 "
        "{%0,%1,%2,%3},{%4,%5,%6,%7},{%8,%9},{%0,%1,%2,%3};"
        : "+f"(c[0]), "+f"(c[1]), "+f"(c[2]), "+f"(c[3])
        : "r"(a[0]), "r"(a[1]), "r"(a[2]), "r"(a[3]), "r"(b[0]), "r"(b[1]));
}
__device__ __forceinline__ float gelu_fast(float x) {
    float u = 0.7978845608028654f * fmaf(0.044715f * x, x * x, x);
    float e = __expf(2.0f * u);
    return 0.5f * x * (1.0f + (1.0f - 2.0f / (e + 1.0f)));
}
__device__ __forceinline__ float gelu_tanh(float x) {
    float x3 = x * x * x;
    return 0.5f * x * (1.0f + tanhf(0.7978845608028654f * (x + 0.044715f * x3)));
}
__device__ __forceinline__ uint32_t pack_h2(float a, float b) {
    __half2 t = __floats2half2_rn(a, b);
    return *reinterpret_cast<uint32_t*>(&t);
}
__device__ __forceinline__ __half2 split_hi2(float a, float b, float& la, float& lb) {
    __half ha = __float2half_rn(a);
    __half hb = __float2half_rn(b);
    la = a - __half2float(ha);
    lb = b - __half2float(hb);
    __half2 h; h.x = ha; h.y = hb;
    return h;
}

// ---------------------------------------------------------------------------
// One 128x64 output tile (R6-proven inner structure).
// ---------------------------------------------------------------------------
__device__ void gemm_tile(uint32_t sb, int bm, int bn,
                          const __half* __restrict__ aHi, const __half* __restrict__ aLo,
                          const __half* __restrict__ bHi, const __half* __restrict__ bLo,
                          const float* __restrict__ bias,
                          float* __restrict__ out,
                          __half* __restrict__ nHi, __half* __restrict__ nLo) {
    const int t = threadIdx.x;
    const int lane = t & 31;
    const int w = t >> 5;
    const int wm = (w >> 1) * 32;
    const int wn = (w & 1) * 32;

    const int a_row = t >> 3;
    const int a_c16 = t & 7;

    auto load_stage = [&](int s, int buf) {
        const int k0 = s * BK;
        const uint32_t stg = sb + (uint32_t)buf * STAGE_BYTES;
#pragma unroll
        for (int p = 0; p < 4; ++p) {
            const int row = p * 32 + a_row;
            const uint32_t so = sw128((uint32_t)row * 128 + a_c16 * 16);
            const size_t gofs = (size_t)(bm + row) * CDIM + k0 + a_c16 * 8;
            cpa16(stg + SA_HI + so, aHi + gofs);
            cpa16(stg + SA_LO + so, aLo + gofs);
        }
#pragma unroll
        for (int p = 0; p < 2; ++p) {
            const int row = p * 32 + a_row;
            const uint32_t so = sw128((uint32_t)row * 128 + a_c16 * 16);
            const size_t gofs = (size_t)(bn + row) * CDIM + k0 + a_c16 * 8;
            cpa16(stg + SB_HI + so, bHi + gofs);
            cpa16(stg + SB_LO + so, bLo + gofs);
        }
    };

    uint32_t a_off[2];
#pragma unroll
    for (int mi = 0; mi < 2; ++mi)
        a_off[mi] = (uint32_t)(wm + mi * 16 + (lane & 15)) * 128 + ((lane >> 4) & 1) * 16;
    uint32_t b_off[2];
#pragma unroll
    for (int g = 0; g < 2; ++g)
        b_off[g] = (uint32_t)(wn + g * 16 + ((lane >> 4) & 1) * 8 + (lane & 7)) * 128 +
                   ((lane >> 3) & 1) * 16;

    float acc[2][4][4];
#pragma unroll
    for (int mi = 0; mi < 2; ++mi)
#pragma unroll
        for (int nf = 0; nf < 4; ++nf)
#pragma unroll
            for (int r = 0; r < 4; ++r) acc[mi][nf][r] = 0.0f;

    load_stage(0, 0); cpa_commit();
    load_stage(1, 1); cpa_commit();

    uint32_t ah[2][4], bh[2][4], ahn[2][4], bhn[2][4], al[2][4], bl[2][4];

#pragma unroll 1
    for (int s = 0; s < KSTAGES; ++s) {
        cpa_wait1();
        __syncthreads();
        const int buf = s & 1;
        const uint32_t stg = sb + (uint32_t)buf * STAGE_BYTES;

#pragma unroll
        for (int mi = 0; mi < 2; ++mi)
            ldsm_x4(ah[mi][0], ah[mi][1], ah[mi][2], ah[mi][3],
                    stg + SA_HI + sw128(a_off[mi]));
#pragma unroll
        for (int g = 0; g < 2; ++g)
            ldsm_x4(bh[g][0], bh[g][1], bh[g][2], bh[g][3],
                    stg + SB_HI + sw128(b_off[g]));

#pragma unroll
        for (int kk = 0; kk < 4; ++kk) {
            const uint32_t kb = kk * 32;
#pragma unroll
            for (int mi = 0; mi < 2; ++mi)
                ldsm_x4(al[mi][0], al[mi][1], al[mi][2], al[mi][3],
                        stg + SA_LO + sw128(a_off[mi] + kb));
#pragma unroll
            for (int g = 0; g < 2; ++g)
                ldsm_x4(bl[g][0], bl[g][1], bl[g][2], bl[g][3],
                        stg + SB_LO + sw128(b_off[g] + kb));
            if (kk < 3) {
                const uint32_t kbn = kb + 32;
#pragma unroll
                for (int mi = 0; mi < 2; ++mi)
                    ldsm_x4(ahn[mi][0], ahn[mi][1], ahn[mi][2], ahn[mi][3],
                            stg + SA_HI + sw128(a_off[mi] + kbn));
#pragma unroll
                for (int g = 0; g < 2; ++g)
                    ldsm_x4(bhn[g][0], bhn[g][1], bhn[g][2], bhn[g][3],
                            stg + SB_HI + sw128(b_off[g] + kbn));
            }
#pragma unroll
            for (int mi = 0; mi < 2; ++mi)
#pragma unroll
                for (int nf = 0; nf < 4; ++nf)
                    mma_f16(acc[mi][nf], ah[mi], &bh[nf >> 1][(nf & 1) * 2]);
#pragma unroll
            for (int mi = 0; mi < 2; ++mi)
#pragma unroll
                for (int nf = 0; nf < 4; ++nf)
                    mma_f16(acc[mi][nf], al[mi], &bh[nf >> 1][(nf & 1) * 2]);
#pragma unroll
            for (int mi = 0; mi < 2; ++mi)
#pragma unroll
                for (int nf = 0; nf < 4; ++nf)
                    mma_f16(acc[mi][nf], ah[mi], &bl[nf >> 1][(nf & 1) * 2]);
            if (kk < 3) {
#pragma unroll
                for (int mi = 0; mi < 2; ++mi)
#pragma unroll
                    for (int r = 0; r < 4; ++r) ah[mi][r] = ahn[mi][r];
#pragma unroll
                for (int g = 0; g < 2; ++g)
#pragma unroll
                    for (int r = 0; r < 4; ++r) bh[g][r] = bhn[g][r];
            }
        }
        __syncthreads();
        if (s + 2 < KSTAGES) load_stage(s + 2, buf);
        cpa_commit();
    }

    const int r0 = bm + wm + (lane >> 2);
    const int cbase = bn + wn + (lane & 3) * 2;
#pragma unroll
    for (int mi = 0; mi < 2; ++mi) {
#pragma unroll
        for (int nf = 0; nf < 4; ++nf) {
            const int c = cbase + nf * 8;
            const float2 bv = *reinterpret_cast<const float2*>(&bias[c]);
            const int ra = r0 + mi * 16;
            const int rb = ra + 8;
            float v0 = gelu_fast(acc[mi][nf][0] + bv.x);
            float v1 = gelu_fast(acc[mi][nf][1] + bv.y);
            float v2 = gelu_fast(acc[mi][nf][2] + bv.x);
            float v3 = gelu_fast(acc[mi][nf][3] + bv.y);
            if (out) {
                *reinterpret_cast<float2*>(&out[(size_t)ra * CDIM + c]) = make_float2(v0, v1);
                *reinterpret_cast<float2*>(&out[(size_t)rb * CDIM + c]) = make_float2(v2, v3);
            }
            if (nHi) {
                float l0, l1, l2, l3;
                __half2 h01 = split_hi2(v0, v1, l0, l1);
                __half2 h23 = split_hi2(v2, v3, l2, l3);
                *reinterpret_cast<__half2*>(&nHi[(size_t)ra * CDIM + c]) = h01;
                *reinterpret_cast<__half2*>(&nHi[(size_t)rb * CDIM + c]) = h23;
                *reinterpret_cast<uint32_t*>(&nLo[(size_t)ra * CDIM + c]) = pack_h2(l0, l1);
                *reinterpret_cast<uint32_t*>(&nLo[(size_t)rb * CDIM + c]) = pack_h2(l2, l3);
            }
        }
    }
}

// ---------------------------------------------------------------------------
// Gating phases (inside megakernel). act reads via __ldcg (L1 not coherent).
// ---------------------------------------------------------------------------
__device__ void gate_phase(char* sm, int b, const float* __restrict__ act,
                           const float* __restrict__ f1w, const float* __restrict__ f1b,
                           const float* __restrict__ f2w, const float* __restrict__ f2b,
                           float* __restrict__ gates) {
    float* ps = (float*)sm;                 // 512
    float* hs = ps + CDIM;                  // 128
    float* lg = hs + HIDN;                  // 1536
    const int t = threadIdx.x;

    {   // pool: 2 channels/thread
        const float* p = act + (size_t)b * HW * CDIM + t * 2;
        float sx = 0.f, sy = 0.f;
#pragma unroll 4
        for (int r = 0; r < HW; ++r) {
            float2 v = __ldcg(reinterpret_cast<const float2*>(p + (size_t)r * CDIM));
            sx += v.x; sy += v.y;
        }
        ps[t * 2]     = sx * (1.0f / HW);
        ps[t * 2 + 1] = sy * (1.0f / HW);
    }
    __syncthreads();

    if (t < HIDN) {
        float acc = f1b[t];
#pragma unroll 8
        for (int k = 0; k < CDIM; ++k)
            acc = fmaf(ps[k], f1w[k * HIDN + t], acc);
        hs[t] = gelu_tanh(acc);
    }
    __syncthreads();

    for (int j = t; j < AANCH * CDIM; j += 256) {
        float a2 = f2b[j];
#pragma unroll 8
        for (int k = 0; k < HIDN; ++k)
            a2 = fmaf(hs[k], f2w[k * (AANCH * CDIM) + j], a2);
        lg[j] = a2;
    }
    __syncthreads();

    for (int c = t; c < CDIM; c += 256) {
        float l0 = lg[c], l1 = lg[CDIM + c], l2 = lg[2 * CDIM + c];
        float m = fmaxf(l0, fmaxf(l1, l2));
        float e0 = expf(l0 - m), e1 = expf(l1 - m), e2 = expf(l2 - m);
        float inv = 1.0f / (e0 + e1 + e2);
        gates[b * AANCH * CDIM + c]            = e0 * inv;
        gates[b * AANCH * CDIM + CDIM + c]     = e1 * inv;
        gates[b * AANCH * CDIM + 2 * CDIM + c] = e2 * inv;
    }
}

__device__ void route_phase(float* __restrict__ nx,
                            const float* __restrict__ a0, const float* __restrict__ a1,
                            const float* __restrict__ a2, const float* __restrict__ gates,
                            float gamma,
                            __half* __restrict__ nhi, __half* __restrict__ nlo) {
    const int per_b = HW * CDIM / 4;
    for (int i = blockIdx.x * 256 + threadIdx.x; i < NELEM / 4; i += NCTA * 256) {
        const int b = i / per_b;
        const int c4 = i & (CDIM / 4 - 1);
        const float4 g0 = __ldcg(reinterpret_cast<const float4*>(&gates[b * AANCH * CDIM + c4 * 4]));
        const float4 g1 = __ldcg(reinterpret_cast<const float4*>(&gates[b * AANCH * CDIM + CDIM + c4 * 4]));
        const float4 g2 = __ldcg(reinterpret_cast<const float4*>(&gates[b * AANCH * CDIM + 2 * CDIM + c4 * 4]));

        float4 v  = __ldcg(reinterpret_cast<const float4*>(nx) + i);
        float4 x0 = __ldcg(reinterpret_cast<const float4*>(a0) + i);
        float4 x1 = __ldcg(reinterpret_cast<const float4*>(a1) + i);
        float4 x2 = __ldcg(reinterpret_cast<const float4*>(a2) + i);

        v.x += gamma * (g0.x * x0.x + g1.x * x1.x + g2.x * x2.x);
        v.y += gamma * (g0.y * x0.y + g1.y * x1.y + g2.y * x2.y);
        v.z += gamma * (g0.z * x0.z + g1.z * x1.z + g2.z * x2.z);
        v.w += gamma * (g0.w * x0.w + g1.w * x1.w + g2.w * x2.w);

        reinterpret_cast<float4*>(nx)[i] = v;

        if (nhi) {
            float l0, l1, l2, l3;
            __half2 h01 = split_hi2(v.x, v.y, l0, l1);
            __half2 h23 = split_hi2(v.z, v.w, l2, l3);
            reinterpret_cast<uint2*>(nhi)[i] = make_uint2(*reinterpret_cast<uint32_t*>(&h01),
                                                          *reinterpret_cast<uint32_t*>(&h23));
            reinterpret_cast<uint2*>(nlo)[i] = make_uint2(pack_h2(l0, l1), pack_h2(l2, l3));
        }
    }
}

// ---------------------------------------------------------------------------
// THE megakernel
// ---------------------------------------------------------------------------
__global__ __launch_bounds__(256, 2)
void stage_mega(const float* __restrict__ bb,
                const float* __restrict__ f1w, const float* __restrict__ f1b,
                const float* __restrict__ f2w, const float* __restrict__ f2b,
                const float* __restrict__ gam,
                float* __restrict__ outp) {
    extern __shared__ char smraw[];
    const uint32_t sbraw = (uint32_t)__cvta_generic_to_shared(smraw);
    const uint32_t sb = (sbraw + 1023u) & ~1023u;
    char* smg = smraw + (sb - sbraw);

    const int bid = blockIdx.x;

#pragma unroll 1
    for (int layer = 0; layer < NLAYER; ++layer) {
        const int inS  = layer & 1;
        const int outS = (layer + 1) & 1;
        const __half* aH = g_Ahi + (size_t)inS * NELEM;
        const __half* aL = g_Alo + (size_t)inS * NELEM;
        const __half* wH = g_Whi + (size_t)layer * CDIM * CDIM;
        const __half* wL = g_Wlo + (size_t)layer * CDIM * CDIM;
        const float* bias = bb + (size_t)layer * CDIM;

        float* dst;
        if      (layer == 1)  dst = g_anc0;
        else if (layer == 4)  dst = g_anc1;
        else if (layer == 9)  dst = g_anc2;
        else if (layer == 17) dst = outp;
        else if (layer == 11 || layer == 14) dst = g_bufA;
        else                  dst = nullptr;

        const bool last = (layer == 17);
        __half* nH = last ? nullptr : g_Ahi + (size_t)outS * NELEM;
        __half* nL = last ? nullptr : g_Alo + (size_t)outS * NELEM;

        // GEMM: statically striped tiles
#pragma unroll 1
        for (int tau = bid; tau < NTILE; tau += NCTA) {
            __syncthreads();   // smem reuse guard between tiles / phases
            const int bm = (tau % 49) * BM;
            const int bn = (tau / 49) * BN;
            gemm_tile(sb, bm, bn, aH, aL, wH, wL, bias, dst, nH, nL);
        }
        grid_sync();

        if (layer == 11 || layer == 14 || layer == 17) {
            const int tt = (layer == 11) ? 0 : (layer == 14) ? 1 : 2;
            if (bid < BATCH)
                gate_phase(smg, bid, dst,
                           f1w + (size_t)tt * CDIM * HIDN,
                           f1b + (size_t)tt * HIDN,
                           f2w + (size_t)tt * HIDN * AANCH * CDIM,
                           f2b + (size_t)tt * AANCH * CDIM,
                           g_gates);
            grid_sync();
            route_phase(dst, g_anc0, g_anc1, g_anc2, g_gates, gam[tt], nH, nL);
            grid_sync();
        }
    }
}

// ---------------------------------------------------------------------------
// Preprocessing kernels (separate launches; L1 flushed at boundaries)
// ---------------------------------------------------------------------------
__global__ void convert_x(const float* __restrict__ x,
                          __half* __restrict__ hi, __half* __restrict__ lo) {
    int i = blockIdx.x * blockDim.x + threadIdx.x;
    if (i >= NELEM / 4) return;
    float4 v = reinterpret_cast<const float4*>(x)[i];
    float l0, l1, l2, l3;
    __half2 h01 = split_hi2(v.x, v.y, l0, l1);
    __half2 h23 = split_hi2(v.z, v.w, l2, l3);
    reinterpret_cast<uint2*>(hi)[i] = make_uint2(*reinterpret_cast<uint32_t*>(&h01),
                                                 *reinterpret_cast<uint32_t*>(&h23));
    reinterpret_cast<uint2*>(lo)[i] = make_uint2(pack_h2(l0, l1), pack_h2(l2, l3));
}

__global__ void convert_w(const float* __restrict__ W,
                          __half* __restrict__ whi, __half* __restrict__ wlo) {
    __shared__ float tile[32][33];
    const int l = blockIdx.z;
    const int kt = blockIdx.y * 32;
    const int nt = blockIdx.x * 32;
    const int tx = threadIdx.x, ty = threadIdx.y;
    const size_t lb = (size_t)l * CDIM * CDIM;
#pragma unroll
    for (int q = 0; q < 4; ++q)
        tile[ty + 8 * q][tx] = W[lb + (size_t)(kt + ty + 8 * q) * CDIM + nt + tx];
    __syncthreads();
#pragma unroll
    for (int q = 0; q < 4; ++q) {
        float v = tile[tx][ty + 8 * q];
        __half h = __float2half_rn(v);
        size_t idx = lb + (size_t)(nt + ty + 8 * q) * CDIM + kt + tx;
        whi[idx] = h;
        wlo[idx] = __float2half_rn(v - __half2float(h));
    }
}

// ---------------------------------------------------------------------------
extern "C" void kernel_launch(void* const* d_in, const int* in_sizes, int n_in,
                              void* d_out, int out_size) {
    const float* x   = (const float*)d_in[0];
    const float* bw  = (const float*)d_in[1];
    const float* bb  = (const float*)d_in[2];
    const float* f1w = (const float*)d_in[3];
    const float* f1b = (const float*)d_in[4];
    const float* f2w = (const float*)d_in[5];
    const float* f2b = (const float*)d_in[6];
    const float* gam = (const float*)d_in[7];

    __half *ahi, *alo, *whi, *wlo;
    cudaGetSymbolAddress((void**)&ahi, g_Ahi);
    cudaGetSymbolAddress((void**)&alo, g_Alo);
    cudaGetSymbolAddress((void**)&whi, g_Whi);
    cudaGetSymbolAddress((void**)&wlo, g_Wlo);

    cudaFuncSetAttribute(stage_mega, cudaFuncAttributeMaxDynamicSharedMemorySize, SMEM_DYN);

    convert_w<<<dim3(CDIM / 32, CDIM / 32, NLAYER), dim3(32, 8)>>>(bw, whi, wlo);
    convert_x<<<(NELEM / 4 + 255) / 256, 256>>>(x, ahi, alo);

    stage_mega<<<NCTA, 256, SMEM_DYN>>>(bb, f1w, f1b, f2w, f2b, gam, (float*)d_out);
}